// round 15
// baseline (speedup 1.0000x reference)
#include <cuda_runtime.h>
#include <cuda_bf16.h>
#include <cstdint>

// Problem constants
#define NB 16
#define NQ 1024
#define NKK 1024
#define DM 512
#define NH 8
#define DKH 64
#define NM 40
#define NKP 1088          // padded key length: 17 * 64
#define ROWS (NB*NQ)      // 16384

// -------- scratch (static device memory: allowed), all 16B-aligned --------
__device__ __align__(256) __nv_bfloat16 g_Ain[3][(size_t)ROWS*DM];    // bf16 inputs
__device__ __align__(256) __nv_bfloat16 g_Qb[(size_t)NB*NH*NQ*DKH];   // pre-scaled bf16
__device__ __align__(256) __nv_bfloat16 g_Kb[(size_t)NB*NH*NKP*DKH];
__device__ __align__(256) __nv_bfloat16 g_Vb[(size_t)NB*NH*NKP*DKH];
__device__ __align__(256) __nv_bfloat16 g_Ob[(size_t)ROWS*DM];
__device__ __align__(256) __nv_bfloat16 g_Wtb[4][(size_t)DM*DM];      // transposed bf16
__device__ __align__(256) float g_X[(size_t)ROWS*DM];

#define QSC (0.125f * 1.4426950408889634f)   // 1/sqrt(dk) * log2(e)

// ============================================================
// helpers
// ============================================================
__device__ __forceinline__ uint32_t smem_u32(const void* p) {
    uint32_t a;
    asm("{ .reg .u64 t; cvta.to.shared.u64 t, %1; cvt.u32.u64 %0, t; }"
        : "=r"(a) : "l"(p));
    return a;
}
__device__ __forceinline__ uint32_t pk2(float lo, float hi) {  // {lo,hi} bf16x2
    uint32_t r;
    asm("cvt.rn.bf16x2.f32 %0, %1, %2;" : "=r"(r) : "f"(hi), "f"(lo));
    return r;
}
__device__ __forceinline__ uint32_t ex2b2(uint32_t x) {        // packed bf16x2 exp2
    uint32_t y;
    asm("ex2.approx.ftz.bf16x2 %0, %1;" : "=r"(y) : "r"(x));
    return y;
}
// sum both bf16 halves of a packed reg in fp32 (shift-expand is exact)
__device__ __forceinline__ float sum2(uint32_t p) {
    return __uint_as_float(p << 16) + __uint_as_float(p & 0xFFFF0000u);
}
__device__ __forceinline__ void mma_bf16(float* c, const uint32_t* a, const uint32_t* b) {
    asm volatile(
        "mma.sync.aligned.m16n8k16.row.col.f32.bf16.bf16.f32 "
        "{%0,%1,%2,%3}, {%4,%5,%6,%7}, {%8,%9}, {%0,%1,%2,%3};"
        : "+f"(c[0]), "+f"(c[1]), "+f"(c[2]), "+f"(c[3])
        : "r"(a[0]), "r"(a[1]), "r"(a[2]), "r"(a[3]), "r"(b[0]), "r"(b[1]));
}
__device__ __forceinline__ void ldsm4(uint32_t* r, uint32_t addr) {
    asm volatile("ldmatrix.sync.aligned.m8n8.x4.shared.b16 {%0,%1,%2,%3}, [%4];"
                 : "=r"(r[0]), "=r"(r[1]), "=r"(r[2]), "=r"(r[3]) : "r"(addr));
}
__device__ __forceinline__ void ldsm4t(uint32_t* r, uint32_t addr) {
    asm volatile("ldmatrix.sync.aligned.m8n8.x4.trans.shared.b16 {%0,%1,%2,%3}, [%4];"
                 : "=r"(r[0]), "=r"(r[1]), "=r"(r[2]), "=r"(r[3]) : "r"(addr));
}
__device__ __forceinline__ void cp16(uint32_t dst, const void* src) {
    asm volatile("cp.async.cg.shared.global [%0], [%1], 16;" :: "r"(dst), "l"(src));
}
#define CP_COMMIT() asm volatile("cp.async.commit_group;")
#define CP_WAIT0()  asm volatile("cp.async.wait_group 0;" ::: "memory")
#define CP_WAIT1()  asm volatile("cp.async.wait_group 1;" ::: "memory")
#define CP_WAIT2()  asm volatile("cp.async.wait_group 2;" ::: "memory")

// ============================================================
// Fused preprocessing: cvt (fp32->bf16, 4x per thread) +
// weight transpose + memfill.
// ============================================================
#define CVT_BLOCKS 6144

__global__ void __launch_bounds__(256) prep_kernel(
    const float* __restrict__ q, const float* __restrict__ k,
    const float* __restrict__ v,
    const float* __restrict__ Wq, const float* __restrict__ Wk,
    const float* __restrict__ Wv, const float* __restrict__ Wo,
    const float* __restrict__ memK, const float* __restrict__ memV)
{
    const int bid = blockIdx.x;
    const int tid = threadIdx.x;

    if (bid < CVT_BLOCKS) {
        const int z = bid / (CVT_BLOCKS/3);
        const int bx = bid - z*(CVT_BLOCKS/3);
        const float* src = (z == 0) ? q : (z == 1) ? k : v;
        __nv_bfloat16* dst = g_Ain[z];
        const size_t base = ((size_t)bx*1024 + tid)*4;
#pragma unroll
        for (int u = 0; u < 4; u++) {
            const size_t i = base + (size_t)u*1024;
            const float4 t = *(const float4*)(src + i);
            uint2 o;
            o.x = pk2(t.x, t.y);
            o.y = pk2(t.z, t.w);
            *(uint2*)(dst + i) = o;
        }
    } else if (bid < CVT_BLOCKS + 1024) {
        __shared__ float t[32][33];
        const int i0 = bid - CVT_BLOCKS;
        const int z = i0 >> 8, by = (i0 >> 4) & 15, bx = i0 & 15;
        const float* W = (z == 0) ? Wq : (z == 1) ? Wk : (z == 2) ? Wv : Wo;
        const int tx = tid & 31, ty = tid >> 5;
        const int nx = bx*32 + tx;
        const int ky = by*32 + ty;
#pragma unroll
        for (int i = 0; i < 32; i += 8)
            t[ty + i][tx] = W[(size_t)(ky + i)*DM + nx];
        __syncthreads();
        const int ok = by*32 + tx;
        const int on = bx*32 + ty;
#pragma unroll
        for (int i = 0; i < 32; i += 8)
            g_Wtb[z][(size_t)(on + i)*DM + ok] = __float2bfloat16(t[tx][ty + i]);
    } else {
        const int bh = bid - CVT_BLOCKS - 1024;
        const int h = bh & 7;
        const float sk = 8.0f;
        const float sv = 6.3245553203367587f;
        for (int idx = tid; idx < 64*64; idx += 256) {
            const int m = idx >> 6;
            const int d = idx & 63;
            float kv = 0.f, vv = 0.f;
            if (m < NM) {
                kv = sk * memK[m*DM + h*DKH + d];
                vv = sv * memV[m*DM + h*DKH + d];
            }
            const size_t o = ((size_t)bh*NKP + 1024 + m)*DKH + d;
            g_Kb[o] = __float2bfloat16(kv);
            g_Vb[o] = __float2bfloat16(vv);
        }
    }
}

// ============================================================
// bf16 mma GEMM (block 128x128, BK=32, 8 warps), cp.async,
// 3-stage ring (lookahead 2), one __syncthreads per K-iter.
// (R12-measured-optimal shape; do not change granularity.)
// ============================================================
#define GROWB 80
#define GBUFB (128*GROWB)
#define GEMM_SMEM (6*GBUFB)

template<int OUTPROJ>
__device__ __forceinline__ void gemm_body(const __nv_bfloat16* __restrict__ Ab,
                                          const __nv_bfloat16* __restrict__ Wb,
                                          const float* __restrict__ bias,
                                          const float* __restrict__ resid,
                                          int z, float scale, char* gsm)
{
    const uint32_t sbase = smem_u32(gsm);
    const int tid = threadIdx.x;
    const int lane = tid & 31, wid = tid >> 5;
    const int wm = (wid & 1) << 6;
    const int wn = (wid >> 1) << 5;
    const int gr = lane >> 2, tc = lane & 3;
    const int m0 = blockIdx.y << 7, n0 = blockIdx.x << 7;

    const int row = tid >> 1, seg = tid & 1;
    const __nv_bfloat16* srcA = Ab + (size_t)(m0 + row)*DM + seg*16;
    const __nv_bfloat16* srcB = Wb + (size_t)(n0 + row)*DM + seg*16;
    const uint32_t dA = sbase + row*GROWB + seg*32;
    const uint32_t dB = dA + 3*GBUFB;

    const int lr16 = lane & 15, lk8 = lane >> 4;

#define G_ISSUE(it, st) do { \
    cp16(dA + (uint32_t)(st)*GBUFB,      srcA + (it)*32); \
    cp16(dA + (uint32_t)(st)*GBUFB + 16, srcA + (it)*32 + 8); \
    cp16(dB + (uint32_t)(st)*GBUFB,      srcB + (it)*32); \
    cp16(dB + (uint32_t)(st)*GBUFB + 16, srcB + (it)*32 + 8); \
    CP_COMMIT(); } while (0)

    float acc[4][4][4];
#pragma unroll
    for (int i = 0; i < 4; i++)
#pragma unroll
        for (int j = 0; j < 4; j++)
#pragma unroll
            for (int r = 0; r < 4; r++) acc[i][j][r] = 0.f;

    G_ISSUE(0, 0);
    G_ISSUE(1, 1);

    for (int it = 0; it < 16; it++) {
        if (it < 15) CP_WAIT1(); else CP_WAIT0();
        __syncthreads();
        if (it + 2 < 16) G_ISSUE(it + 2, (it + 2) % 3);

        const uint32_t so = (uint32_t)(it % 3)*GBUFB;
        const uint32_t a_ld = sbase + so + (wm + lr16)*GROWB + lk8*16;
        const uint32_t b_ld = sbase + 3*GBUFB + so + (wn + lr16)*GROWB + lk8*16;
#pragma unroll
        for (int ks = 0; ks < 2; ks++) {
            uint32_t a[4][4], b[4][2];
#pragma unroll
            for (int i = 0; i < 4; i++)
                ldsm4(a[i], a_ld + i*16*GROWB + ks*32);
#pragma unroll
            for (int jp = 0; jp < 2; jp++) {
                uint32_t t[4];
                ldsm4(t, b_ld + jp*16*GROWB + ks*32);
                b[2*jp][0]   = t[0]; b[2*jp+1][0] = t[1];
                b[2*jp][1]   = t[2]; b[2*jp+1][1] = t[3];
            }
#pragma unroll
            for (int i = 0; i < 4; i++)
#pragma unroll
                for (int j = 0; j < 4; j++)
                    mma_bf16(acc[i][j], a[i], b[j]);
        }
    }
#undef G_ISSUE

#pragma unroll
    for (int i = 0; i < 4; i++) {
        const int mA = m0 + wm + i*16 + gr;
        const int mB = mA + 8;
#pragma unroll
        for (int j = 0; j < 4; j++) {
            const int n = n0 + wn + j*8 + 2*tc;
            const float b0 = bias[n], b1 = bias[n+1];
            if (OUTPROJ) {
                float2 vA = make_float2(acc[i][j][0] + b0, acc[i][j][1] + b1);
                float2 vB = make_float2(acc[i][j][2] + b0, acc[i][j][3] + b1);
                const float2 rA = *(const float2*)(resid + (size_t)mA*DM + n);
                const float2 rB = *(const float2*)(resid + (size_t)mB*DM + n);
                vA.x += rA.x; vA.y += rA.y;
                vB.x += rB.x; vB.y += rB.y;
                *(float2*)(&g_X[(size_t)mA*DM + n]) = vA;
                *(float2*)(&g_X[(size_t)mB*DM + n]) = vB;
            } else {
                const uint32_t pA = pk2((acc[i][j][0] + b0)*scale,
                                        (acc[i][j][1] + b1)*scale);
                const uint32_t pB = pk2((acc[i][j][2] + b0)*scale,
                                        (acc[i][j][3] + b1)*scale);
                const int h = n >> 6, d = n & 63;
                const int bbA = mA >> 10, nnA = mA & 1023;
                const int bbB = mB >> 10, nnB = mB & 1023;
                if (z == 0) {
                    *(uint32_t*)(&g_Qb[(((size_t)bbA*NH + h)*NQ + nnA)*DKH + d]) = pA;
                    *(uint32_t*)(&g_Qb[(((size_t)bbB*NH + h)*NQ + nnB)*DKH + d]) = pB;
                } else if (z == 1) {
                    *(uint32_t*)(&g_Kb[(((size_t)bbA*NH + h)*NKP + nnA)*DKH + d]) = pA;
                    *(uint32_t*)(&g_Kb[(((size_t)bbB*NH + h)*NKP + nnB)*DKH + d]) = pB;
                } else {
                    *(uint32_t*)(&g_Vb[(((size_t)bbA*NH + h)*NKP + nnA)*DKH + d]) = pA;
                    *(uint32_t*)(&g_Vb[(((size_t)bbB*NH + h)*NKP + nnB)*DKH + d]) = pB;
                }
            }
        }
    }
}

__global__ void __launch_bounds__(256, 2) gemm_qkv(const float* __restrict__ bq,
                                                   const float* __restrict__ bk,
                                                   const float* __restrict__ bv)
{
    extern __shared__ char gsm[];
    const int z = blockIdx.z;
    const float* bias = (z == 0) ? bq : (z == 1) ? bk : bv;
    const float scale = (z == 0) ? QSC : 1.0f;
    gemm_body<0>(g_Ain[z], g_Wtb[z], bias, nullptr, z, scale, gsm);
}

__global__ void __launch_bounds__(256, 2) gemm_out(const float* __restrict__ bias,
                                                   const float* __restrict__ resid)
{
    extern __shared__ char gsm[];
    gemm_body<1>(g_Ob, g_Wtb[3], bias, resid, 3, 1.0f, gsm);
}

// ============================================================
// bf16 flash attention: block = (b,h) x 128 queries, 8 warps.
// 3-stage cp.async K/V ring (1 sync/tile). Fixed-reference
// log2 softmax, packed bf16x2 exp2. Row sums computed on the
// (idle) ALU pipe from the packed P registers (exact bf16->fp32
// shift-expand + fp32 adds) -- frees 4 mmas/warp-tile on the
// saturated tensor pipe vs the R12 P@ones scheme.
// ============================================================
#define AROWB 144
#define KVB (64*AROWB)
#define STGB (2*KVB)
#define ATT_SMEM (3*STGB)

__global__ void __launch_bounds__(256, 2) attn_mma_kernel(const float* __restrict__ AW)
{
    extern __shared__ char asmm[];
    const uint32_t sb = smem_u32(asmm);

    const int tid = threadIdx.x, lane = tid & 31, wid = tid >> 5;
    const int bh = blockIdx.y, b = bh >> 3, h = bh & 7;
    const int q0 = blockIdx.x << 7;
    const int gr = lane >> 2, tc = lane & 3;
    const int qw = wid << 4;
    const int lr16 = lane & 15, lk8 = lane >> 4;
    const uint32_t sQ = sb + 2*STGB;   // Q staged in stage-2 region

    // ---- issue Q (pre-scaled bf16 in gmem) ----
    {
        const int r = tid >> 1, qs = tid & 1;
        const __nv_bfloat16* src = g_Qb + ((size_t)bh*NQ + q0 + r)*DKH + qs*32;
        const uint32_t dst = sQ + r*AROWB + qs*64;
        cp16(dst, src); cp16(dst + 16, src + 8);
        cp16(dst + 32, src + 16); cp16(dst + 48, src + 24);
        CP_COMMIT();
    }

    // ---- K/V issue config ----
    const int rr = tid >> 2, c4 = tid & 3;
    const __nv_bfloat16* kgp = g_Kb + ((size_t)bh*NKP + rr)*DKH + c4*16;
    const __nv_bfloat16* vgp = g_Vb + ((size_t)bh*NKP + rr)*DKH + c4*16;
    const uint32_t kvdst = rr*AROWB + c4*32;

#define A_ISSUE(kt, st) do { \
    const __nv_bfloat16* ks_ = kgp + (size_t)(kt)*64*DKH; \
    const __nv_bfloat16* vs_ = vgp + (size_t)(kt)*64*DKH; \
    const uint32_t kd = sb + (uint32_t)(st)*STGB + kvdst; \
    cp16(kd, ks_); cp16(kd + 16, ks_ + 8); \
    cp16(kd + KVB, vs_); cp16(kd + KVB + 16, vs_ + 8); \
    CP_COMMIT(); } while (0)

    A_ISSUE(0, 0);
    A_ISSUE(1, 1);
    CP_WAIT2();            // Q arrived
    __syncthreads();

    uint32_t qf[4][4];
#pragma unroll
    for (int ks = 0; ks < 4; ks++)
        ldsm4(qf[ks], sQ + (qw + lr16)*AROWB + lk8*16 + ks*32);
    // stage-2 (Q area) first overwritten by A_ISSUE(2), after the
    // loop-top __syncthreads -> qf reads are safe.

    float o[8][4];
#pragma unroll
    for (int j = 0; j < 8; j++)
#pragma unroll
        for (int r = 0; r < 4; r++) o[j][r] = 0.f;
    float l0 = 0.f, l1 = 0.f;

    for (int kt = 0; kt < 17; kt++) {
        if (kt < 16) CP_WAIT1(); else CP_WAIT0();
        __syncthreads();
        if (kt + 2 <= 16) A_ISSUE(kt + 2, (kt + 2) % 3);

        const uint32_t sK = sb + (uint32_t)(kt % 3)*STGB;
        const uint32_t sV = sK + KVB;

        // ---- S = Qs @ K^T (log2 domain) ----
        float sc[8][4];
#pragma unroll
        for (int j = 0; j < 8; j++)
            sc[j][0] = sc[j][1] = sc[j][2] = sc[j][3] = 0.f;
#pragma unroll
        for (int ks = 0; ks < 4; ks++) {
#pragma unroll
            for (int jp = 0; jp < 4; jp++) {
                uint32_t t[4];
                ldsm4(t, sK + (jp*16 + lr16)*AROWB + lk8*16 + ks*32);
                uint32_t b0[2] = {t[0], t[2]};
                uint32_t b1[2] = {t[1], t[3]};
                mma_bf16(sc[2*jp],   qf[ks], b0);
                mma_bf16(sc[2*jp+1], qf[ks], b1);
            }
        }

        // ---- attention_weights / memory mask ----
        if (kt < 16) {
            const float* aw0 = AW + ((size_t)b*NQ + q0 + qw + gr)*NKK + kt*64 + 2*tc;
            const float* aw1 = aw0 + 8*(size_t)NKK;
#pragma unroll
            for (int j = 0; j < 8; j++) {
                const float2 w0 = *(const float2*)(aw0 + j*8);
                const float2 w1 = *(const float2*)(aw1 + j*8);
                sc[j][0] *= w0.x; sc[j][1] *= w0.y;
                sc[j][2] *= w1.x; sc[j][3] *= w1.y;
            }
        } else {
#pragma unroll
            for (int j = 0; j < 8; j++) {
                const int c = j*8 + 2*tc;
                if (c >= NM)     { sc[j][0] = -1e30f; sc[j][2] = -1e30f; }
                if (c + 1 >= NM) { sc[j][1] = -1e30f; sc[j][3] = -1e30f; }
            }
        }

        // ---- softmax: pack sc pairs to bf16x2, packed exp2 -> P frags ----
        uint32_t pa[4][4];
#pragma unroll
        for (int t2 = 0; t2 < 4; t2++) {
            pa[t2][0] = ex2b2(pk2(sc[2*t2][0],   sc[2*t2][1]));
            pa[t2][1] = ex2b2(pk2(sc[2*t2][2],   sc[2*t2][3]));
            pa[t2][2] = ex2b2(pk2(sc[2*t2+1][0], sc[2*t2+1][1]));
            pa[t2][3] = ex2b2(pk2(sc[2*t2+1][2], sc[2*t2+1][3]));
        }

        // ---- row sums on the ALU pipe (exact bf16->fp32 expand) ----
        {
            float s0 = 0.f, s1 = 0.f;
#pragma unroll
            for (int t2 = 0; t2 < 4; t2++) {
                s0 += sum2(pa[t2][0]) + sum2(pa[t2][2]);   // row gr
                s1 += sum2(pa[t2][1]) + sum2(pa[t2][3]);   // row gr+8
            }
            s0 += __shfl_xor_sync(0xffffffffu, s0, 1);
            s0 += __shfl_xor_sync(0xffffffffu, s0, 2);
            s1 += __shfl_xor_sync(0xffffffffu, s1, 1);
            s1 += __shfl_xor_sync(0xffffffffu, s1, 2);
            l0 += s0;
            l1 += s1;
        }

        // ---- O += P @ V ----
#pragma unroll
        for (int ks = 0; ks < 4; ks++) {
#pragma unroll
            for (int jp = 0; jp < 4; jp++) {
                uint32_t t[4];
                ldsm4t(t, sV + (ks*16 + ((lane>>3)&1)*8 + (lane&7))*AROWB
                            + (jp*16 + lk8*8)*2);
                uint32_t b0[2] = {t[0], t[1]};
                uint32_t b1[2] = {t[2], t[3]};
                mma_bf16(o[2*jp],   pa[ks], b0);
                mma_bf16(o[2*jp+1], pa[ks], b1);
            }
        }
    }
#undef A_ISSUE

    // ---- normalize + write bf16 O ----
    const float inv0 = 1.0f / l0, inv1 = 1.0f / l1;
    __nv_bfloat16* op0 = g_Ob + ((size_t)b*NQ + q0 + qw + gr)*DM + h*DKH + 2*tc;
    __nv_bfloat16* op1 = op0 + 8*(size_t)DM;
#pragma unroll
    for (int j = 0; j < 8; j++) {
        *(uint32_t*)(op0 + j*8) = pk2(o[j][0]*inv0, o[j][1]*inv0);
        *(uint32_t*)(op1 + j*8) = pk2(o[j][2]*inv1, o[j][3]*inv1);
    }
}

// ============================================================
// LayerNorm: warp per row, 2 rows per warp pass, eps=1e-3
// ============================================================
__global__ void __launch_bounds__(256) ln_kernel(const float* __restrict__ gamma,
                                                 const float* __restrict__ beta,
                                                 float* __restrict__ out)
{
    const int warp = blockIdx.x*8 + (threadIdx.x >> 5);
    const int lane = threadIdx.x & 31;
#pragma unroll
    for (int rr = 0; rr < 2; rr++) {
        const int row = warp*2 + rr;
        const float* xr = g_X + (size_t)row*DM;
        float v[16];
        float s = 0.f, s2 = 0.f;
#pragma unroll
        for (int u = 0; u < 4; u++) {
            const float4 t = *(const float4*)(xr + lane*4 + u*128);
            v[4*u+0] = t.x; v[4*u+1] = t.y; v[4*u+2] = t.z; v[4*u+3] = t.w;
            s  += t.x + t.y + t.z + t.w;
            s2 += t.x*t.x + t.y*t.y + t.z*t.z + t.w*t.w;
        }
#pragma unroll
        for (int off = 16; off > 0; off >>= 1) {
            s  += __shfl_xor_sync(0xffffffffu, s,  off);
            s2 += __shfl_xor_sync(0xffffffffu, s2, off);
        }
        const float mu  = s * (1.f/512.f);
        const float var = s2 * (1.f/512.f) - mu*mu;
        const float rs  = rsqrtf(var + 1e-3f);
        float* orow = out + (size_t)row*DM;
#pragma unroll
        for (int u = 0; u < 4; u++) {
            const int d = lane*4 + u*128;
            const float4 g  = *(const float4*)(gamma + d);
            const float4 bt = *(const float4*)(beta + d);
            float4 r;
            r.x = g.x*(v[4*u+0]-mu)*rs + bt.x;
            r.y = g.y*(v[4*u+1]-mu)*rs + bt.y;
            r.z = g.z*(v[4*u+2]-mu)*rs + bt.z;
            r.w = g.w*(v[4*u+3]-mu)*rs + bt.w;
            *(float4*)(orow + d) = r;
        }
    }
}

// ============================================================
extern "C" void kernel_launch(void* const* d_in, const int* in_sizes, int n_in,
                              void* d_out, int out_size)
{
    (void)in_sizes; (void)n_in; (void)out_size;
    const float* queries = (const float*)d_in[0];
    const float* keys    = (const float*)d_in[1];
    const float* values  = (const float*)d_in[2];
    const float* aw      = (const float*)d_in[3];
    const float* bq = (const float*)d_in[5];
    const float* bk = (const float*)d_in[7];
    const float* bv = (const float*)d_in[9];
    const float* bo = (const float*)d_in[11];
    const float* memK = (const float*)d_in[12];
    const float* memV = (const float*)d_in[13];
    const float* gamma = (const float*)d_in[14];
    const float* beta  = (const float*)d_in[15];
    float* out = (float*)d_out;

    cudaFuncSetAttribute(gemm_qkv, cudaFuncAttributeMaxDynamicSharedMemorySize, GEMM_SMEM);
    cudaFuncSetAttribute(gemm_out, cudaFuncAttributeMaxDynamicSharedMemorySize, GEMM_SMEM);
    cudaFuncSetAttribute(attn_mma_kernel, cudaFuncAttributeMaxDynamicSharedMemorySize, ATT_SMEM);

    prep_kernel<<<CVT_BLOCKS + 1024 + 128, 256>>>(
        queries, keys, values,
        (const float*)d_in[4], (const float*)d_in[6],
        (const float*)d_in[8], (const float*)d_in[10],
        memK, memV);
    gemm_qkv<<<dim3(4, 128, 3), 256, GEMM_SMEM>>>(bq, bk, bv);
    attn_mma_kernel<<<dim3(8, 128), 256, ATT_SMEM>>>(aw);
    gemm_out<<<dim3(4, 128), 256, GEMM_SMEM>>>(bo, queries);
    ln_kernel<<<ROWS/16, 256>>>(gamma, beta, out);
}

// round 16
// speedup vs baseline: 1.0198x; 1.0198x over previous
#include <cuda_runtime.h>
#include <cuda_bf16.h>
#include <cstdint>

// Problem constants
#define NB 16
#define NQ 1024
#define NKK 1024
#define DM 512
#define NH 8
#define DKH 64
#define NM 40
#define NKP 1088          // padded key length: 17 * 64
#define ROWS (NB*NQ)      // 16384

// -------- scratch (static device memory: allowed), all 16B-aligned --------
__device__ __align__(256) __nv_bfloat16 g_Ain[3][(size_t)ROWS*DM];    // bf16 inputs
__device__ __align__(256) __nv_bfloat16 g_Qb[(size_t)NB*NH*NQ*DKH];   // pre-scaled bf16
__device__ __align__(256) __nv_bfloat16 g_Kb[(size_t)NB*NH*NKP*DKH];
__device__ __align__(256) __nv_bfloat16 g_Vb[(size_t)NB*NH*NKP*DKH];
__device__ __align__(256) __nv_bfloat16 g_Ob[(size_t)ROWS*DM];
__device__ __align__(256) __nv_bfloat16 g_Wtb[4][(size_t)DM*DM];      // transposed bf16
__device__ __align__(256) float g_X[(size_t)ROWS*DM];

#define QSC (0.125f * 1.4426950408889634f)   // 1/sqrt(dk) * log2(e)

// ============================================================
// helpers
// ============================================================
__device__ __forceinline__ uint32_t smem_u32(const void* p) {
    uint32_t a;
    asm("{ .reg .u64 t; cvta.to.shared.u64 t, %1; cvt.u32.u64 %0, t; }"
        : "=r"(a) : "l"(p));
    return a;
}
__device__ __forceinline__ uint32_t pk2(float lo, float hi) {  // {lo,hi} bf16x2
    uint32_t r;
    asm("cvt.rn.bf16x2.f32 %0, %1, %2;" : "=r"(r) : "f"(hi), "f"(lo));
    return r;
}
__device__ __forceinline__ uint32_t ex2b2(uint32_t x) {        // packed bf16x2 exp2
    uint32_t y;
    asm("ex2.approx.ftz.bf16x2 %0, %1;" : "=r"(y) : "r"(x));
    return y;
}
__device__ __forceinline__ void mma_bf16(float* c, const uint32_t* a, const uint32_t* b) {
    asm volatile(
        "mma.sync.aligned.m16n8k16.row.col.f32.bf16.bf16.f32 "
        "{%0,%1,%2,%3}, {%4,%5,%6,%7}, {%8,%9}, {%0,%1,%2,%3};"
        : "+f"(c[0]), "+f"(c[1]), "+f"(c[2]), "+f"(c[3])
        : "r"(a[0]), "r"(a[1]), "r"(a[2]), "r"(a[3]), "r"(b[0]), "r"(b[1]));
}
__device__ __forceinline__ void ldsm4(uint32_t* r, uint32_t addr) {
    asm volatile("ldmatrix.sync.aligned.m8n8.x4.shared.b16 {%0,%1,%2,%3}, [%4];"
                 : "=r"(r[0]), "=r"(r[1]), "=r"(r[2]), "=r"(r[3]) : "r"(addr));
}
__device__ __forceinline__ void ldsm4t(uint32_t* r, uint32_t addr) {
    asm volatile("ldmatrix.sync.aligned.m8n8.x4.trans.shared.b16 {%0,%1,%2,%3}, [%4];"
                 : "=r"(r[0]), "=r"(r[1]), "=r"(r[2]), "=r"(r[3]) : "r"(addr));
}
__device__ __forceinline__ void cp16(uint32_t dst, const void* src) {
    asm volatile("cp.async.cg.shared.global [%0], [%1], 16;" :: "r"(dst), "l"(src));
}
#define CP_COMMIT() asm volatile("cp.async.commit_group;")
#define CP_WAIT0()  asm volatile("cp.async.wait_group 0;" ::: "memory")
#define CP_WAIT1()  asm volatile("cp.async.wait_group 1;" ::: "memory")
#define CP_WAIT2()  asm volatile("cp.async.wait_group 2;" ::: "memory")

// ============================================================
// Fused preprocessing: cvt (fp32->bf16, 4x per thread) +
// weight transpose + memfill.
// ============================================================
#define CVT_BLOCKS 6144

__global__ void __launch_bounds__(256) prep_kernel(
    const float* __restrict__ q, const float* __restrict__ k,
    const float* __restrict__ v,
    const float* __restrict__ Wq, const float* __restrict__ Wk,
    const float* __restrict__ Wv, const float* __restrict__ Wo,
    const float* __restrict__ memK, const float* __restrict__ memV)
{
    const int bid = blockIdx.x;
    const int tid = threadIdx.x;

    if (bid < CVT_BLOCKS) {
        const int z = bid / (CVT_BLOCKS/3);
        const int bx = bid - z*(CVT_BLOCKS/3);
        const float* src = (z == 0) ? q : (z == 1) ? k : v;
        __nv_bfloat16* dst = g_Ain[z];
        const size_t base = ((size_t)bx*1024 + tid)*4;
#pragma unroll
        for (int u = 0; u < 4; u++) {
            const size_t i = base + (size_t)u*1024;
            const float4 t = *(const float4*)(src + i);
            uint2 o;
            o.x = pk2(t.x, t.y);
            o.y = pk2(t.z, t.w);
            *(uint2*)(dst + i) = o;
        }
    } else if (bid < CVT_BLOCKS + 1024) {
        __shared__ float t[32][33];
        const int i0 = bid - CVT_BLOCKS;
        const int z = i0 >> 8, by = (i0 >> 4) & 15, bx = i0 & 15;
        const float* W = (z == 0) ? Wq : (z == 1) ? Wk : (z == 2) ? Wv : Wo;
        const int tx = tid & 31, ty = tid >> 5;
        const int nx = bx*32 + tx;
        const int ky = by*32 + ty;
#pragma unroll
        for (int i = 0; i < 32; i += 8)
            t[ty + i][tx] = W[(size_t)(ky + i)*DM + nx];
        __syncthreads();
        const int ok = by*32 + tx;
        const int on = bx*32 + ty;
#pragma unroll
        for (int i = 0; i < 32; i += 8)
            g_Wtb[z][(size_t)(on + i)*DM + ok] = __float2bfloat16(t[tx][ty + i]);
    } else {
        const int bh = bid - CVT_BLOCKS - 1024;
        const int h = bh & 7;
        const float sk = 8.0f;
        const float sv = 6.3245553203367587f;
        for (int idx = tid; idx < 64*64; idx += 256) {
            const int m = idx >> 6;
            const int d = idx & 63;
            float kv = 0.f, vv = 0.f;
            if (m < NM) {
                kv = sk * memK[m*DM + h*DKH + d];
                vv = sv * memV[m*DM + h*DKH + d];
            }
            const size_t o = ((size_t)bh*NKP + 1024 + m)*DKH + d;
            g_Kb[o] = __float2bfloat16(kv);
            g_Vb[o] = __float2bfloat16(vv);
        }
    }
}

// ============================================================
// bf16 mma GEMM (block 128x128, BK=32, 8 warps), cp.async,
// 3-stage ring (lookahead 2), one __syncthreads per K-iter.
// (R12-measured-optimal shape; do not change granularity.)
// ============================================================
#define GROWB 80
#define GBUFB (128*GROWB)
#define GEMM_SMEM (6*GBUFB)

template<int OUTPROJ>
__device__ __forceinline__ void gemm_body(const __nv_bfloat16* __restrict__ Ab,
                                          const __nv_bfloat16* __restrict__ Wb,
                                          const float* __restrict__ bias,
                                          const float* __restrict__ resid,
                                          int z, float scale, char* gsm)
{
    const uint32_t sbase = smem_u32(gsm);
    const int tid = threadIdx.x;
    const int lane = tid & 31, wid = tid >> 5;
    const int wm = (wid & 1) << 6;
    const int wn = (wid >> 1) << 5;
    const int gr = lane >> 2, tc = lane & 3;
    const int m0 = blockIdx.y << 7, n0 = blockIdx.x << 7;

    const int row = tid >> 1, seg = tid & 1;
    const __nv_bfloat16* srcA = Ab + (size_t)(m0 + row)*DM + seg*16;
    const __nv_bfloat16* srcB = Wb + (size_t)(n0 + row)*DM + seg*16;
    const uint32_t dA = sbase + row*GROWB + seg*32;
    const uint32_t dB = dA + 3*GBUFB;

    const int lr16 = lane & 15, lk8 = lane >> 4;

#define G_ISSUE(it, st) do { \
    cp16(dA + (uint32_t)(st)*GBUFB,      srcA + (it)*32); \
    cp16(dA + (uint32_t)(st)*GBUFB + 16, srcA + (it)*32 + 8); \
    cp16(dB + (uint32_t)(st)*GBUFB,      srcB + (it)*32); \
    cp16(dB + (uint32_t)(st)*GBUFB + 16, srcB + (it)*32 + 8); \
    CP_COMMIT(); } while (0)

    float acc[4][4][4];
#pragma unroll
    for (int i = 0; i < 4; i++)
#pragma unroll
        for (int j = 0; j < 4; j++)
#pragma unroll
            for (int r = 0; r < 4; r++) acc[i][j][r] = 0.f;

    G_ISSUE(0, 0);
    G_ISSUE(1, 1);

    for (int it = 0; it < 16; it++) {
        if (it < 15) CP_WAIT1(); else CP_WAIT0();
        __syncthreads();
        if (it + 2 < 16) G_ISSUE(it + 2, (it + 2) % 3);

        const uint32_t so = (uint32_t)(it % 3)*GBUFB;
        const uint32_t a_ld = sbase + so + (wm + lr16)*GROWB + lk8*16;
        const uint32_t b_ld = sbase + 3*GBUFB + so + (wn + lr16)*GROWB + lk8*16;
#pragma unroll
        for (int ks = 0; ks < 2; ks++) {
            uint32_t a[4][4], b[4][2];
#pragma unroll
            for (int i = 0; i < 4; i++)
                ldsm4(a[i], a_ld + i*16*GROWB + ks*32);
#pragma unroll
            for (int jp = 0; jp < 2; jp++) {
                uint32_t t[4];
                ldsm4(t, b_ld + jp*16*GROWB + ks*32);
                b[2*jp][0]   = t[0]; b[2*jp+1][0] = t[1];
                b[2*jp][1]   = t[2]; b[2*jp+1][1] = t[3];
            }
#pragma unroll
            for (int i = 0; i < 4; i++)
#pragma unroll
                for (int j = 0; j < 4; j++)
                    mma_bf16(acc[i][j], a[i], b[j]);
        }
    }
#undef G_ISSUE

#pragma unroll
    for (int i = 0; i < 4; i++) {
        const int mA = m0 + wm + i*16 + gr;
        const int mB = mA + 8;
#pragma unroll
        for (int j = 0; j < 4; j++) {
            const int n = n0 + wn + j*8 + 2*tc;
            const float b0 = bias[n], b1 = bias[n+1];
            if (OUTPROJ) {
                float2 vA = make_float2(acc[i][j][0] + b0, acc[i][j][1] + b1);
                float2 vB = make_float2(acc[i][j][2] + b0, acc[i][j][3] + b1);
                const float2 rA = *(const float2*)(resid + (size_t)mA*DM + n);
                const float2 rB = *(const float2*)(resid + (size_t)mB*DM + n);
                vA.x += rA.x; vA.y += rA.y;
                vB.x += rB.x; vB.y += rB.y;
                *(float2*)(&g_X[(size_t)mA*DM + n]) = vA;
                *(float2*)(&g_X[(size_t)mB*DM + n]) = vB;
            } else {
                const uint32_t pA = pk2((acc[i][j][0] + b0)*scale,
                                        (acc[i][j][1] + b1)*scale);
                const uint32_t pB = pk2((acc[i][j][2] + b0)*scale,
                                        (acc[i][j][3] + b1)*scale);
                const int h = n >> 6, d = n & 63;
                const int bbA = mA >> 10, nnA = mA & 1023;
                const int bbB = mB >> 10, nnB = mB & 1023;
                if (z == 0) {
                    *(uint32_t*)(&g_Qb[(((size_t)bbA*NH + h)*NQ + nnA)*DKH + d]) = pA;
                    *(uint32_t*)(&g_Qb[(((size_t)bbB*NH + h)*NQ + nnB)*DKH + d]) = pB;
                } else if (z == 1) {
                    *(uint32_t*)(&g_Kb[(((size_t)bbA*NH + h)*NKP + nnA)*DKH + d]) = pA;
                    *(uint32_t*)(&g_Kb[(((size_t)bbB*NH + h)*NKP + nnB)*DKH + d]) = pB;
                } else {
                    *(uint32_t*)(&g_Vb[(((size_t)bbA*NH + h)*NKP + nnA)*DKH + d]) = pA;
                    *(uint32_t*)(&g_Vb[(((size_t)bbB*NH + h)*NKP + nnB)*DKH + d]) = pB;
                }
            }
        }
    }
}

__global__ void __launch_bounds__(256, 2) gemm_qkv(const float* __restrict__ bq,
                                                   const float* __restrict__ bk,
                                                   const float* __restrict__ bv)
{
    extern __shared__ char gsm[];
    const int z = blockIdx.z;
    const float* bias = (z == 0) ? bq : (z == 1) ? bk : bv;
    const float scale = (z == 0) ? QSC : 1.0f;
    gemm_body<0>(g_Ain[z], g_Wtb[z], bias, nullptr, z, scale, gsm);
}

__global__ void __launch_bounds__(256, 2) gemm_out(const float* __restrict__ bias,
                                                   const float* __restrict__ resid)
{
    extern __shared__ char gsm[];
    gemm_body<1>(g_Ob, g_Wtb[3], bias, resid, 3, 1.0f, gsm);
}

// ============================================================
// bf16 flash attention: block = (b,h) x 128 queries, 8 warps.
// 3-stage cp.async K/V ring (1 sync/tile). Fixed-reference
// log2 softmax, packed bf16x2 exp2, row sums via P @ ones.
// (R14-measured-optimal; AW row pointers hoisted out of loop.)
// ============================================================
#define AROWB 144
#define KVB (64*AROWB)
#define STGB (2*KVB)
#define ATT_SMEM (3*STGB)

__global__ void __launch_bounds__(256, 2) attn_mma_kernel(const float* __restrict__ AW)
{
    extern __shared__ char asmm[];
    const uint32_t sb = smem_u32(asmm);

    const int tid = threadIdx.x, lane = tid & 31, wid = tid >> 5;
    const int bh = blockIdx.y, b = bh >> 3, h = bh & 7;
    const int q0 = blockIdx.x << 7;
    const int gr = lane >> 2, tc = lane & 3;
    const int qw = wid << 4;
    const int lr16 = lane & 15, lk8 = lane >> 4;
    const uint32_t sQ = sb + 2*STGB;   // Q staged in stage-2 region

    // ---- issue Q (pre-scaled bf16 in gmem) ----
    {
        const int r = tid >> 1, qs = tid & 1;
        const __nv_bfloat16* src = g_Qb + ((size_t)bh*NQ + q0 + r)*DKH + qs*32;
        const uint32_t dst = sQ + r*AROWB + qs*64;
        cp16(dst, src); cp16(dst + 16, src + 8);
        cp16(dst + 32, src + 16); cp16(dst + 48, src + 24);
        CP_COMMIT();
    }

    // ---- K/V issue config ----
    const int rr = tid >> 2, c4 = tid & 3;
    const __nv_bfloat16* kgp = g_Kb + ((size_t)bh*NKP + rr)*DKH + c4*16;
    const __nv_bfloat16* vgp = g_Vb + ((size_t)bh*NKP + rr)*DKH + c4*16;
    const uint32_t kvdst = rr*AROWB + c4*32;

#define A_ISSUE(kt, st) do { \
    const __nv_bfloat16* ks_ = kgp + (size_t)(kt)*64*DKH; \
    const __nv_bfloat16* vs_ = vgp + (size_t)(kt)*64*DKH; \
    const uint32_t kd = sb + (uint32_t)(st)*STGB + kvdst; \
    cp16(kd, ks_); cp16(kd + 16, ks_ + 8); \
    cp16(kd + KVB, vs_); cp16(kd + KVB + 16, vs_ + 8); \
    CP_COMMIT(); } while (0)

    A_ISSUE(0, 0);
    A_ISSUE(1, 1);
    CP_WAIT2();            // Q arrived
    __syncthreads();

    uint32_t qf[4][4];
#pragma unroll
    for (int ks = 0; ks < 4; ks++)
        ldsm4(qf[ks], sQ + (qw + lr16)*AROWB + lk8*16 + ks*32);
    // stage-2 (Q area) first overwritten by A_ISSUE(2), after the
    // loop-top __syncthreads -> qf reads are safe.

    float o[8][4];
#pragma unroll
    for (int j = 0; j < 8; j++)
#pragma unroll
        for (int r = 0; r < 4; r++) o[j][r] = 0.f;
    float osum[4] = {0.f, 0.f, 0.f, 0.f};
    const uint32_t ones[2] = {0x3F803F80u, 0x3F803F80u};

    // hoisted AW row pointers (advance by 64 floats per tile)
    const float* aw0 = AW + ((size_t)b*NQ + q0 + qw + gr)*NKK + 2*tc;
    const float* aw1 = aw0 + 8*(size_t)NKK;

    for (int kt = 0; kt < 17; kt++) {
        if (kt < 16) CP_WAIT1(); else CP_WAIT0();
        __syncthreads();
        if (kt + 2 <= 16) A_ISSUE(kt + 2, (kt + 2) % 3);

        const uint32_t sK = sb + (uint32_t)(kt % 3)*STGB;
        const uint32_t sV = sK + KVB;

        // ---- S = Qs @ K^T (log2 domain) ----
        float sc[8][4];
#pragma unroll
        for (int j = 0; j < 8; j++)
            sc[j][0] = sc[j][1] = sc[j][2] = sc[j][3] = 0.f;
#pragma unroll
        for (int ks = 0; ks < 4; ks++) {
#pragma unroll
            for (int jp = 0; jp < 4; jp++) {
                uint32_t t[4];
                ldsm4(t, sK + (jp*16 + lr16)*AROWB + lk8*16 + ks*32);
                uint32_t b0[2] = {t[0], t[2]};
                uint32_t b1[2] = {t[1], t[3]};
                mma_bf16(sc[2*jp],   qf[ks], b0);
                mma_bf16(sc[2*jp+1], qf[ks], b1);
            }
        }

        // ---- attention_weights / memory mask ----
        if (kt < 16) {
#pragma unroll
            for (int j = 0; j < 8; j++) {
                const float2 w0 = *(const float2*)(aw0 + j*8);
                const float2 w1 = *(const float2*)(aw1 + j*8);
                sc[j][0] *= w0.x; sc[j][1] *= w0.y;
                sc[j][2] *= w1.x; sc[j][3] *= w1.y;
            }
            aw0 += 64;
            aw1 += 64;
        } else {
#pragma unroll
            for (int j = 0; j < 8; j++) {
                const int c = j*8 + 2*tc;
                if (c >= NM)     { sc[j][0] = -1e30f; sc[j][2] = -1e30f; }
                if (c + 1 >= NM) { sc[j][1] = -1e30f; sc[j][3] = -1e30f; }
            }
        }

        // ---- softmax: pack sc pairs to bf16x2, packed exp2 -> P frags ----
        uint32_t pa[4][4];
#pragma unroll
        for (int t2 = 0; t2 < 4; t2++) {
            pa[t2][0] = ex2b2(pk2(sc[2*t2][0],   sc[2*t2][1]));
            pa[t2][1] = ex2b2(pk2(sc[2*t2][2],   sc[2*t2][3]));
            pa[t2][2] = ex2b2(pk2(sc[2*t2+1][0], sc[2*t2+1][1]));
            pa[t2][3] = ex2b2(pk2(sc[2*t2+1][2], sc[2*t2+1][3]));
        }

        // ---- row sums: osum += P @ ones ----
#pragma unroll
        for (int ks = 0; ks < 4; ks++)
            mma_bf16(osum, pa[ks], ones);

        // ---- O += P @ V ----
#pragma unroll
        for (int ks = 0; ks < 4; ks++) {
#pragma unroll
            for (int jp = 0; jp < 4; jp++) {
                uint32_t t[4];
                ldsm4t(t, sV + (ks*16 + ((lane>>3)&1)*8 + (lane&7))*AROWB
                            + (jp*16 + lk8*8)*2);
                uint32_t b0[2] = {t[0], t[1]};
                uint32_t b1[2] = {t[2], t[3]};
                mma_bf16(o[2*jp],   pa[ks], b0);
                mma_bf16(o[2*jp+1], pa[ks], b1);
            }
        }
    }
#undef A_ISSUE

    // ---- normalize + write bf16 O ----
    const float inv0 = 1.0f / osum[0], inv1 = 1.0f / osum[2];
    __nv_bfloat16* op0 = g_Ob + ((size_t)b*NQ + q0 + qw + gr)*DM + h*DKH + 2*tc;
    __nv_bfloat16* op1 = op0 + 8*(size_t)DM;
#pragma unroll
    for (int j = 0; j < 8; j++) {
        *(uint32_t*)(op0 + j*8) = pk2(o[j][0]*inv0, o[j][1]*inv0);
        *(uint32_t*)(op1 + j*8) = pk2(o[j][2]*inv1, o[j][3]*inv1);
    }
}

// ============================================================
// LayerNorm: warp per row, 2 rows per warp pass, eps=1e-3
// ============================================================
__global__ void __launch_bounds__(256) ln_kernel(const float* __restrict__ gamma,
                                                 const float* __restrict__ beta,
                                                 float* __restrict__ out)
{
    const int warp = blockIdx.x*8 + (threadIdx.x >> 5);
    const int lane = threadIdx.x & 31;
#pragma unroll
    for (int rr = 0; rr < 2; rr++) {
        const int row = warp*2 + rr;
        const float* xr = g_X + (size_t)row*DM;
        float v[16];
        float s = 0.f, s2 = 0.f;
#pragma unroll
        for (int u = 0; u < 4; u++) {
            const float4 t = *(const float4*)(xr + lane*4 + u*128);
            v[4*u+0] = t.x; v[4*u+1] = t.y; v[4*u+2] = t.z; v[4*u+3] = t.w;
            s  += t.x + t.y + t.z + t.w;
            s2 += t.x*t.x + t.y*t.y + t.z*t.z + t.w*t.w;
        }
#pragma unroll
        for (int off = 16; off > 0; off >>= 1) {
            s  += __shfl_xor_sync(0xffffffffu, s,  off);
            s2 += __shfl_xor_sync(0xffffffffu, s2, off);
        }
        const float mu  = s * (1.f/512.f);
        const float var = s2 * (1.f/512.f) - mu*mu;
        const float rs  = rsqrtf(var + 1e-3f);
        float* orow = out + (size_t)row*DM;
#pragma unroll
        for (int u = 0; u < 4; u++) {
            const int d = lane*4 + u*128;
            const float4 g  = *(const float4*)(gamma + d);
            const float4 bt = *(const float4*)(beta + d);
            float4 r;
            r.x = g.x*(v[4*u+0]-mu)*rs + bt.x;
            r.y = g.y*(v[4*u+1]-mu)*rs + bt.y;
            r.z = g.z*(v[4*u+2]-mu)*rs + bt.z;
            r.w = g.w*(v[4*u+3]-mu)*rs + bt.w;
            *(float4*)(orow + d) = r;
        }
    }
}

// ============================================================
extern "C" void kernel_launch(void* const* d_in, const int* in_sizes, int n_in,
                              void* d_out, int out_size)
{
    (void)in_sizes; (void)n_in; (void)out_size;
    const float* queries = (const float*)d_in[0];
    const float* keys    = (const float*)d_in[1];
    const float* values  = (const float*)d_in[2];
    const float* aw      = (const float*)d_in[3];
    const float* bq = (const float*)d_in[5];
    const float* bk = (const float*)d_in[7];
    const float* bv = (const float*)d_in[9];
    const float* bo = (const float*)d_in[11];
    const float* memK = (const float*)d_in[12];
    const float* memV = (const float*)d_in[13];
    const float* gamma = (const float*)d_in[14];
    const float* beta  = (const float*)d_in[15];
    float* out = (float*)d_out;

    cudaFuncSetAttribute(gemm_qkv, cudaFuncAttributeMaxDynamicSharedMemorySize, GEMM_SMEM);
    cudaFuncSetAttribute(gemm_out, cudaFuncAttributeMaxDynamicSharedMemorySize, GEMM_SMEM);
    cudaFuncSetAttribute(attn_mma_kernel, cudaFuncAttributeMaxDynamicSharedMemorySize, ATT_SMEM);

    prep_kernel<<<CVT_BLOCKS + 1024 + 128, 256>>>(
        queries, keys, values,
        (const float*)d_in[4], (const float*)d_in[6],
        (const float*)d_in[8], (const float*)d_in[10],
        memK, memV);
    gemm_qkv<<<dim3(4, 128, 3), 256, GEMM_SMEM>>>(bq, bk, bv);
    attn_mma_kernel<<<dim3(8, 128), 256, ATT_SMEM>>>(aw);
    gemm_out<<<dim3(4, 128), 256, GEMM_SMEM>>>(bo, queries);
    ln_kernel<<<ROWS/16, 256>>>(gamma, beta, out);
}